// round 5
// baseline (speedup 1.0000x reference)
#include <cuda_runtime.h>
#include <cstdint>

// Quincunx lattice max pooling — 8-wide (2×float4) per-thread variant.
// Inputs: coset0, coset1 each [B=4, C=32, H=512, W=512] f32.
// Output: [2, B, C, H, W] f32 (out0 stacked before out1).
//
// out0[i,j] = max(c0[i,j], c0[i+1,j], c0[i,j+1], c0[i+1,j+1], c1[i,j])
// out1[i,j] = max(c1[i,j], c1[i+1,j], c1[i,j+1], c1[i+1,j+1], c0[i+1,j+1])
// Out-of-range -> -inf.
//
// Each thread handles columns [8g, 8g+8) of one row: the j+4 edge of the
// low float4 is the high float4's .x (in registers); only the j+8 edge
// needs a scalar load. Streaming stores (outputs never re-read).

#define NEG_INF __int_as_float(0xff800000)

__device__ __forceinline__ float fmax5(float a, float b, float c, float d, float e) {
    return fmaxf(fmaxf(fmaxf(a, b), fmaxf(c, d)), e);
}

// Computes one output row-pair-of-float4 given own rows (r0 lo/hi, r1 lo/hi),
// cross (x lo/hi) and the scalar edges.
__device__ __forceinline__ void pool8(
    float4 r0l, float4 r0h, float r0e,
    float4 r1l, float4 r1h, float r1e,
    float4 xl,  float4 xh,
    float4& ol, float4& oh)
{
    ol.x = fmax5(r0l.x, r0l.y, r1l.x, r1l.y, xl.x);
    ol.y = fmax5(r0l.y, r0l.z, r1l.y, r1l.z, xl.y);
    ol.z = fmax5(r0l.z, r0l.w, r1l.z, r1l.w, xl.z);
    ol.w = fmax5(r0l.w, r0h.x, r1l.w, r1h.x, xl.w);
    oh.x = fmax5(r0h.x, r0h.y, r1h.x, r1h.y, xh.x);
    oh.y = fmax5(r0h.y, r0h.z, r1h.y, r1h.z, xh.y);
    oh.z = fmax5(r0h.z, r0h.w, r1h.z, r1h.w, xh.z);
    oh.w = fmax5(r0h.w, r0e,   r1h.w, r1e,   xh.w);
}

// planes = B*C = 128, H = 512, groups of 8 cols = 64 per row.
// total threads = 128 * 512 * 64 = 4194304.
__global__ void __launch_bounds__(256) lattice_pool_kernel(
    const float4* __restrict__ c0,
    const float4* __restrict__ c1,
    float4* __restrict__ out0,
    float4* __restrict__ out1)
{
    const unsigned idx = blockIdx.x * blockDim.x + threadIdx.x;
    const unsigned g = idx & 63;            // 8-column group
    const unsigned i = (idx >> 6) & 511;    // row

    // vec index of low float4: plane*65536 + i*128 + 2g = 2*idx - ... actually:
    // idx = p*32768 + i*64 + g  ->  pos = p*65536 + i*128 + 2g = 2*idx - 0? 2*idx = p*65536+i*128+2g. Yes.
    const unsigned pos = 2u * idx;

    const bool hasRow = (i < 511);
    const bool hasCol = (g < 63);

    const unsigned posR = hasRow ? pos + 128u : pos;

    // Row i (lo/hi) and row i+1 (lo/hi) of both cosets.
    float4 a0l = c0[pos],      a0h = c0[pos + 1u];
    float4 b0l = c1[pos],      b0h = c1[pos + 1u];
    float4 a1l = c0[posR],     a1h = c0[posR + 1u];
    float4 b1l = c1[posR],     b1h = c1[posR + 1u];
    if (!hasRow) {
        const float4 NI4 = make_float4(NEG_INF, NEG_INF, NEG_INF, NEG_INF);
        a1l = NI4; a1h = NI4; b1l = NI4; b1h = NI4;
    }

    // j+8 edge scalars (first element of the next group's low float4).
    const float* c0f = (const float*)c0;
    const float* c1f = (const float*)c1;
    const unsigned f = (pos + 2u) << 2;   // float index of element j+8, row i
    float a0e = hasCol ? c0f[f] : NEG_INF;
    float b0e = hasCol ? c1f[f] : NEG_INF;
    float a1e = (hasCol && hasRow) ? c0f[f + 512u] : NEG_INF;
    float b1e = (hasCol && hasRow) ? c1f[f + 512u] : NEG_INF;

    float4 ol, oh;
    // out0: own = c0 rows i,i+1; cross = c1 row i.
    pool8(a0l, a0h, a0e, a1l, a1h, a1e, b0l, b0h, ol, oh);
    __stcs(&out0[pos], ol);
    __stcs(&out0[pos + 1u], oh);

    // out1: own = c1 rows i,i+1; cross = c0 row i+1 shifted (1,1):
    // cross element at out col j is a1[j+1]; build shifted lo/hi vectors.
    float4 xl, xh;
    xl.x = a1l.y; xl.y = a1l.z; xl.z = a1l.w; xl.w = a1h.x;
    xh.x = a1h.y; xh.y = a1h.z; xh.z = a1h.w; xh.w = a1e;
    pool8(b0l, b0h, b0e, b1l, b1h, b1e, xl, xh, ol, oh);
    __stcs(&out1[pos], ol);
    __stcs(&out1[pos + 1u], oh);
}

extern "C" void kernel_launch(void* const* d_in, const int* in_sizes, int n_in,
                              void* d_out, int out_size) {
    const float4* c0 = (const float4*)d_in[0];
    const float4* c1 = (const float4*)d_in[1];
    float4* out0 = (float4*)d_out;
    float4* out1 = out0 + 8388608;  // B*C*H*W / 4 float4 elements

    const int total = 4194304;      // 128 planes * 512 rows * 64 groups
    const int threads = 256;
    const int blocks = total / threads; // 16384
    lattice_pool_kernel<<<blocks, threads>>>(c0, c1, out0, out1);
}

// round 6
// speedup vs baseline: 1.0114x; 1.0114x over previous
#include <cuda_runtime.h>
#include <cstdint>

// Quincunx lattice max pooling — final roofline version (R4 winner, block=512).
// Inputs: coset0, coset1 each [B=4, C=32, H=512, W=512] f32.
// Output: [2, B, C, H, W] f32 (out0 stacked before out1).
//
// out0[i,j] = max(c0[i,j], c0[i+1,j], c0[i,j+1], c0[i+1,j+1], c1[i,j])
// out1[i,j] = max(c1[i,j], c1[i+1,j], c1[i,j+1], c1[i+1,j+1], c0[i+1,j+1])
// Out-of-range -> -inf.
//
// One float4 per thread per output coset; fully coalesced LDG.128/STG.128
// (16B inter-lane stride). Row i+1 re-reads hit L2. Outputs use streaming
// stores (__stcs): never re-read, keep L2 for input row reuse.

#define NEG_INF __int_as_float(0xff800000)

__device__ __forceinline__ float fmax5(float a, float b, float c, float d, float e) {
    return fmaxf(fmaxf(fmaxf(a, b), fmaxf(c, d)), e);
}

// H = W = 512, W4 = 128 (float4 lanes per row), planes = B*C = 128.
__global__ void __launch_bounds__(512) lattice_pool_kernel(
    const float4* __restrict__ c0,
    const float4* __restrict__ c1,
    float4* __restrict__ out0,
    float4* __restrict__ out1)
{
    const int idx = blockIdx.x * blockDim.x + threadIdx.x;
    const int jv = idx & 127;          // float4 column
    const int i  = (idx >> 7) & 511;   // row

    const size_t pos = (size_t)idx;    // fully linear layout

    const bool hasRow = (i < 511);
    const bool hasCol = (jv < 127);

    // Row i+1 loads: clamp offset instead of predicating the load, so both
    // LDG.128 pairs issue unconditionally (front-batched).
    const size_t posR = hasRow ? pos + 128 : pos;

    float4 a0 = c0[pos];
    float4 b0 = c1[pos];
    float4 a1 = c0[posR];
    float4 b1 = c1[posR];
    if (!hasRow) {
        a1 = make_float4(NEG_INF, NEG_INF, NEG_INF, NEG_INF);
        b1 = make_float4(NEG_INF, NEG_INF, NEG_INF, NEG_INF);
    }

    // Column j+4 scalars (first element of neighbor float4) — L1 hits.
    const float* c0f = (const float*)c0;
    const float* c1f = (const float*)c1;
    const size_t fbase = (pos << 2) + 4;   // float index of element j+4, row i
    float a0e = hasCol ? c0f[fbase] : NEG_INF;
    float b0e = hasCol ? c1f[fbase] : NEG_INF;
    float a1e = (hasCol && hasRow) ? c0f[fbase + 512] : NEG_INF;
    float b1e = (hasCol && hasRow) ? c1f[fbase + 512] : NEG_INF;

    float4 o0, o1;
    // out0: own = c0, cross = c1[i,j]
    o0.x = fmax5(a0.x, a0.y, a1.x, a1.y, b0.x);
    o0.y = fmax5(a0.y, a0.z, a1.y, a1.z, b0.y);
    o0.z = fmax5(a0.z, a0.w, a1.z, a1.w, b0.z);
    o0.w = fmax5(a0.w, a0e,  a1.w, a1e,  b0.w);
    // out1: own = c1, cross = c0[i+1,j+1]
    o1.x = fmax5(b0.x, b0.y, b1.x, b1.y, a1.y);
    o1.y = fmax5(b0.y, b0.z, b1.y, b1.z, a1.z);
    o1.z = fmax5(b0.z, b0.w, b1.z, b1.w, a1.w);
    o1.w = fmax5(b0.w, b0e,  b1.w, b1e,  a1e);

    __stcs(&out0[pos], o0);   // streaming store: output never re-read
    __stcs(&out1[pos], o1);
}

extern "C" void kernel_launch(void* const* d_in, const int* in_sizes, int n_in,
                              void* d_out, int out_size) {
    const float4* c0 = (const float4*)d_in[0];
    const float4* c1 = (const float4*)d_in[1];
    float4* out0 = (float4*)d_out;
    float4* out1 = out0 + 8388608;  // B*C*H*W / 4 float4 elements

    const int total = 8388608;      // 128 planes * 512 rows * 128 vec-cols
    const int threads = 512;
    const int blocks = total / threads; // 16384
    lattice_pool_kernel<<<blocks, threads>>>(c0, c1, out0, out1);
}

// round 7
// speedup vs baseline: 1.0251x; 1.0135x over previous
#include <cuda_runtime.h>
#include <cstdint>

// Quincunx lattice max pooling — FINAL (measured best: R4 config).
// Inputs: coset0, coset1 each [B=4, C=32, H=512, W=512] f32.
// Output: [2, B, C, H, W] f32 (out0 stacked before out1).
//
// out0[i,j] = max(c0[i,j], c0[i+1,j], c0[i,j+1], c0[i+1,j+1], c1[i,j])
// out1[i,j] = max(c1[i,j], c1[i+1,j], c1[i,j+1], c1[i+1,j+1], c0[i+1,j+1])
// Out-of-range -> -inf.
//
// One float4 per thread per output coset; fully coalesced LDG.128/STG.128
// (16B inter-lane stride). Row i+1 re-reads hit L2 (adjacent-row blocks are
// temporally close). Outputs use streaming stores (__stcs): never re-read,
// keeps L2 capacity for input row reuse. Measured: 6.46 TB/s, traffic at the
// 512 MB analytic minimum — HBM-roofline bound.

#define NEG_INF __int_as_float(0xff800000)

__device__ __forceinline__ float fmax5(float a, float b, float c, float d, float e) {
    return fmaxf(fmaxf(fmaxf(a, b), fmaxf(c, d)), e);
}

// H = W = 512, W4 = 128 (float4 lanes per row), planes = B*C = 128.
__global__ void __launch_bounds__(256) lattice_pool_kernel(
    const float4* __restrict__ c0,
    const float4* __restrict__ c1,
    float4* __restrict__ out0,
    float4* __restrict__ out1)
{
    const int idx = blockIdx.x * blockDim.x + threadIdx.x;
    const int jv = idx & 127;          // float4 column
    const int i  = (idx >> 7) & 511;   // row

    const size_t pos = (size_t)idx;    // fully linear layout

    const bool hasRow = (i < 511);
    const bool hasCol = (jv < 127);

    // Row i+1 loads: clamp offset instead of predicating the load, so both
    // LDG.128 pairs issue unconditionally (front-batched).
    const size_t posR = hasRow ? pos + 128 : pos;

    float4 a0 = c0[pos];
    float4 b0 = c1[pos];
    float4 a1 = c0[posR];
    float4 b1 = c1[posR];
    if (!hasRow) {
        a1 = make_float4(NEG_INF, NEG_INF, NEG_INF, NEG_INF);
        b1 = make_float4(NEG_INF, NEG_INF, NEG_INF, NEG_INF);
    }

    // Column j+4 scalars (first element of neighbor float4) — L1 hits.
    const float* c0f = (const float*)c0;
    const float* c1f = (const float*)c1;
    const size_t fbase = (pos << 2) + 4;   // float index of element j+4, row i
    float a0e = hasCol ? c0f[fbase] : NEG_INF;
    float b0e = hasCol ? c1f[fbase] : NEG_INF;
    float a1e = (hasCol && hasRow) ? c0f[fbase + 512] : NEG_INF;
    float b1e = (hasCol && hasRow) ? c1f[fbase + 512] : NEG_INF;

    float4 o0, o1;
    // out0: own = c0, cross = c1[i,j]
    o0.x = fmax5(a0.x, a0.y, a1.x, a1.y, b0.x);
    o0.y = fmax5(a0.y, a0.z, a1.y, a1.z, b0.y);
    o0.z = fmax5(a0.z, a0.w, a1.z, a1.w, b0.z);
    o0.w = fmax5(a0.w, a0e,  a1.w, a1e,  b0.w);
    // out1: own = c1, cross = c0[i+1,j+1]
    o1.x = fmax5(b0.x, b0.y, b1.x, b1.y, a1.y);
    o1.y = fmax5(b0.y, b0.z, b1.y, b1.z, a1.z);
    o1.z = fmax5(b0.z, b0.w, b1.z, b1.w, a1.w);
    o1.w = fmax5(b0.w, b0e,  b1.w, b1e,  a1e);

    __stcs(&out0[pos], o0);   // streaming store: output never re-read
    __stcs(&out1[pos], o1);
}

extern "C" void kernel_launch(void* const* d_in, const int* in_sizes, int n_in,
                              void* d_out, int out_size) {
    const float4* c0 = (const float4*)d_in[0];
    const float4* c1 = (const float4*)d_in[1];
    float4* out0 = (float4*)d_out;
    float4* out1 = out0 + 8388608;  // B*C*H*W / 4 float4 elements

    const int total = 8388608;      // 128 planes * 512 rows * 128 vec-cols
    const int threads = 256;
    const int blocks = total / threads; // 32768
    lattice_pool_kernel<<<blocks, threads>>>(c0, c1, out0, out1);
}

// round 8
// speedup vs baseline: 1.0255x; 1.0004x over previous
#include <cuda_runtime.h>
#include <cstdint>

// Quincunx lattice max pooling — FINAL (measured best across 6 variants).
// Inputs: coset0, coset1 each [B=4, C=32, H=512, W=512] f32.
// Output: [2, B, C, H, W] f32 (out0 stacked before out1).
//
// out0[i,j] = max(c0[i,j], c0[i+1,j], c0[i,j+1], c0[i+1,j+1], c1[i,j])
// out1[i,j] = max(c1[i,j], c1[i+1,j], c1[i,j+1], c1[i+1,j+1], c0[i+1,j+1])
// Out-of-range -> -inf.
//
// One float4 per thread per output coset; fully coalesced LDG.128/STG.128
// (16B inter-lane stride). Row i+1 re-reads hit L2 (adjacent-row blocks are
// temporally close). Outputs use streaming stores (__stcs): never re-read,
// keeps L2 capacity for input row reuse.
//
// Measured: 6.46 TB/s (81% of 8 TB/s spec), DRAM traffic 482 MB vs 512 MB
// analytic minimum — HBM-roofline bound with a 50/50 r/w mix. Variants
// tested and rejected: row-pair+shuffle (neutral), 8-wide/thread (regressed,
// broke lane coalescing), block=512 (slight regression).

#define NEG_INF __int_as_float(0xff800000)

__device__ __forceinline__ float fmax5(float a, float b, float c, float d, float e) {
    return fmaxf(fmaxf(fmaxf(a, b), fmaxf(c, d)), e);
}

// H = W = 512, W4 = 128 (float4 lanes per row), planes = B*C = 128.
__global__ void __launch_bounds__(256) lattice_pool_kernel(
    const float4* __restrict__ c0,
    const float4* __restrict__ c1,
    float4* __restrict__ out0,
    float4* __restrict__ out1)
{
    const int idx = blockIdx.x * blockDim.x + threadIdx.x;
    const int jv = idx & 127;          // float4 column
    const int i  = (idx >> 7) & 511;   // row

    const size_t pos = (size_t)idx;    // fully linear layout

    const bool hasRow = (i < 511);
    const bool hasCol = (jv < 127);

    // Row i+1 loads: clamp offset instead of predicating the load, so both
    // LDG.128 pairs issue unconditionally (front-batched).
    const size_t posR = hasRow ? pos + 128 : pos;

    float4 a0 = c0[pos];
    float4 b0 = c1[pos];
    float4 a1 = c0[posR];
    float4 b1 = c1[posR];
    if (!hasRow) {
        a1 = make_float4(NEG_INF, NEG_INF, NEG_INF, NEG_INF);
        b1 = make_float4(NEG_INF, NEG_INF, NEG_INF, NEG_INF);
    }

    // Column j+4 scalars (first element of neighbor float4) — L1 hits.
    const float* c0f = (const float*)c0;
    const float* c1f = (const float*)c1;
    const size_t fbase = (pos << 2) + 4;   // float index of element j+4, row i
    float a0e = hasCol ? c0f[fbase] : NEG_INF;
    float b0e = hasCol ? c1f[fbase] : NEG_INF;
    float a1e = (hasCol && hasRow) ? c0f[fbase + 512] : NEG_INF;
    float b1e = (hasCol && hasRow) ? c1f[fbase + 512] : NEG_INF;

    float4 o0, o1;
    // out0: own = c0, cross = c1[i,j]
    o0.x = fmax5(a0.x, a0.y, a1.x, a1.y, b0.x);
    o0.y = fmax5(a0.y, a0.z, a1.y, a1.z, b0.y);
    o0.z = fmax5(a0.z, a0.w, a1.z, a1.w, b0.z);
    o0.w = fmax5(a0.w, a0e,  a1.w, a1e,  b0.w);
    // out1: own = c1, cross = c0[i+1,j+1]
    o1.x = fmax5(b0.x, b0.y, b1.x, b1.y, a1.y);
    o1.y = fmax5(b0.y, b0.z, b1.y, b1.z, a1.z);
    o1.z = fmax5(b0.z, b0.w, b1.z, b1.w, a1.w);
    o1.w = fmax5(b0.w, b0e,  b1.w, b1e,  a1e);

    __stcs(&out0[pos], o0);   // streaming store: output never re-read
    __stcs(&out1[pos], o1);
}

extern "C" void kernel_launch(void* const* d_in, const int* in_sizes, int n_in,
                              void* d_out, int out_size) {
    const float4* c0 = (const float4*)d_in[0];
    const float4* c1 = (const float4*)d_in[1];
    float4* out0 = (float4*)d_out;
    float4* out1 = out0 + 8388608;  // B*C*H*W / 4 float4 elements

    const int total = 8388608;      // 128 planes * 512 rows * 128 vec-cols
    const int threads = 256;
    const int blocks = total / threads; // 32768
    lattice_pool_kernel<<<blocks, threads>>>(c0, c1, out0, out1);
}